// round 16
// baseline (speedup 1.0000x reference)
#include <cuda_runtime.h>
#include <cuda_fp16.h>
#include <cstdint>

#define B_DIM 1024
#define C_DIM 20
#define LC    5120
#define KC64  80           // LC / 64 K-chunks
#define TSCALE 256.0f
#define NT_TILES 3200      // prep_T tiles: 80(i) x 40(j)
#define NITEMS 480         // quad work items

// ---------------------------------------------------------------------------
// Scratch: FRAGMENT-BLOCKED fp16 layout.
// Block (rg, kc, sp) = 128 words (512B): word (g*16 + q*4 + e) holds the
// fp16 pair (row = rg*8+g, k-pair (c,pc)) with c = sp*2+(e>>1),
// pc = (e&1)*4+q  (k = kc*64 + c*16 + 2*pc {+1}).
// This makes each warp MMA fragment ONE coalesced 512B LDG.128:
// lane(g*4+q) reads words [g*16+q*4, +4) = lane*16B. Element e of the lane's
// uint4 is bit-identical to the old smem fragment element e (proof:
// c*2+(pc>>2) = sp*4+e and pc&3=q hold under both mappings).
// g_Tp zero-initialized; masked tiles never written -> stay zero.
// ---------------------------------------------------------------------------
__device__ uint32_t g_Xp[(size_t)B_DIM * LC / 2];
__device__ uint32_t g_Tp[(size_t)LC * LC / 2];
__device__ int4     g_items[NITEMS];

__device__ __forceinline__ void mma_f16(float c[4],
                                        uint32_t a0, uint32_t a1,
                                        uint32_t a2, uint32_t a3,
                                        uint32_t b0, uint32_t b1) {
    asm("mma.sync.aligned.m16n8k16.row.col.f32.f16.f16.f32 "
        "{%0,%1,%2,%3}, {%4,%5,%6,%7}, {%8,%9}, {%0,%1,%2,%3};"
        : "+f"(c[0]), "+f"(c[1]), "+f"(c[2]), "+f"(c[3])
        : "r"(a0), "r"(a1), "r"(a2), "r"(a3), "r"(b0), "r"(b1));
}

__device__ __forceinline__ int kpp_of(int jt) {
    const int Kmax = ((jt * 128 + 127) / C_DIM) * C_DIM;
    return (Kmax + 63) >> 6;
}

// ---------------------------------------------------------------------------
// Merged prep kernel: prep_T tiles (fragment-blocked), prep_X + init out,
// and the LPT quad schedule (first prep_X block).
// ---------------------------------------------------------------------------
__global__ __launch_bounds__(256)
void prep_all(const float* __restrict__ X,
              const float* __restrict__ th0,
              const float* __restrict__ thlc,
              const float* __restrict__ T,
              float* __restrict__ out) {
    const int blk = blockIdx.x;
    const int t   = threadIdx.x;

    if (blk < NT_TILES) {
        // ------- prep_T: transpose+scale+convert into fragment blocks -------
        const int it = blk % (LC / 64);          // kc chunk (i tile of 64)
        const int jt = blk / (LC / 64);          // j tile of 128
        const int i0 = it * 64;
        const int j0 = jt * 128;
        const int bound = ((j0 + 127) / C_DIM) * C_DIM;
        if (i0 >= bound) return;                  // fully-masked tile

        __shared__ float tile[64][132];
        {
            const int row = t >> 2;
            const int c16 = t & 3;
            const float* src = T + (size_t)(i0 + row) * LC + j0;
            #pragma unroll
            for (int rr = 0; rr < 8; rr++) {
                const int col4 = c16 + rr * 4;
                const float4 v = *reinterpret_cast<const float4*>(src + col4 * 4);
                *reinterpret_cast<float4*>(&tile[row][col4 * 4]) = v;
            }
        }
        __syncthreads();

        // thread owns (jl, sp): writes 64B = 16 words
        const int jl = t >> 1;                    // 0..127
        const int sp = t & 1;
        const int rg = (j0 >> 3) + (jl >> 3);
        const int g  = jl & 7;
        uint32_t buf[16];
        #pragma unroll
        for (int w16 = 0; w16 < 16; w16++) {
            const int q  = w16 >> 2;
            const int e  = w16 & 3;
            const int c  = sp * 2 + (e >> 1);
            const int pc = (e & 1) * 4 + q;
            const int pl = c * 8 + pc;            // pair index in 64-chunk
            const float v0 = tile[2 * pl][jl] * TSCALE;
            const float v1 = tile[2 * pl + 1][jl] * TSCALE;
            __half2 h = __floats2half2_rn(v0, v1);
            buf[w16] = *reinterpret_cast<uint32_t*>(&h);
        }
        uint32_t* dst = g_Tp + (((size_t)rg * KC64 + it) * 2 + sp) * 128 + g * 16;
        #pragma unroll
        for (int v = 0; v < 4; v++)
            *reinterpret_cast<uint4*>(dst + v * 4) =
                *reinterpret_cast<const uint4*>(&buf[v * 4]);
    } else {
        const int b = blk - NT_TILES;

        if (b == 0) {
            for (int idx = t; idx < NITEMS; idx += 256) {
                int is = 0, ifu = 0, base = 0;
                int jt = 0, bt = 0, kc0 = 0, len = 0;
                for (int step = 0; step < 60; step++) {
                    int lenS = -1, kppS = 0, jtS = 0;
                    if (is < 40) {
                        jtS  = 39 - (is >> 1);
                        kppS = kpp_of(jtS);
                        lenS = (is & 1) ? (kppS >> 1) : (kppS - (kppS >> 1));
                    }
                    int lenF = -1, jtF = 0;
                    if (ifu < 20) { jtF = 19 - ifu; lenF = kpp_of(jtF); }
                    const bool takeS = (is < 40) && (ifu >= 20 || lenS >= lenF);
                    if (idx < base + 8) {
                        bt = idx - base;
                        if (takeS) {
                            jt  = jtS;
                            len = lenS;
                            kc0 = (is & 1) ? (kppS - (kppS >> 1)) : 0;
                        } else {
                            jt = jtF; len = lenF; kc0 = 0;
                        }
                        break;
                    }
                    base += 8;
                    if (takeS) is++; else ifu++;
                }
                g_items[idx] = make_int4(jt, bt, kc0, len);
            }
        }

        // ------- prep_X: fragment-blocked convert + init out -------
        const float* xr = X + (size_t)b * LC;
        float s = 0.f;
        for (int k4 = t; k4 < LC / 4; k4 += 256) {
            const float4 xv = *reinterpret_cast<const float4*>(xr + k4 * 4);
            const float4 tv = *reinterpret_cast<const float4*>(thlc + k4 * 4);
            s += xv.x * tv.x + xv.y * tv.y + xv.z * tv.z + xv.w * tv.w;
            const int k   = k4 * 4;
            const int kc  = k >> 6;
            const int kl  = k & 63;
            const int c   = kl >> 4;
            const int sp  = c >> 1;
            const int pc0 = (kl & 15) >> 1;       // even: 0,2,4,6
            const int q0  = pc0 & 3;
            const int e0  = (c & 1) * 2 + (pc0 >> 2);
            const int pc1 = pc0 + 1;
            const int q1  = pc1 & 3;
            const int e1  = (c & 1) * 2 + (pc1 >> 2);
            uint32_t* base = g_Xp + (((size_t)(b >> 3) * KC64 + kc) * 2 + sp) * 128
                                  + (b & 7) * 16;
            __half2 h0 = __floats2half2_rn(xv.x, xv.y);
            __half2 h1 = __floats2half2_rn(xv.z, xv.w);
            base[q0 * 4 + e0] = *reinterpret_cast<uint32_t*>(&h0);
            base[q1 * 4 + e1] = *reinterpret_cast<uint32_t*>(&h1);
        }
        for (int o = 16; o > 0; o >>= 1) s += __shfl_xor_sync(0xffffffffu, s, o);
        __shared__ float red[8];
        if ((t & 31) == 0) red[t >> 5] = s;
        __syncthreads();
        if (t == 0) {
            float tt = 0.f;
            #pragma unroll
            for (int w = 0; w < 8; w++) tt += red[w];
            out[b] = th0[0] + tt;
        }
    }
}

// ---------------------------------------------------------------------------
// quad kernel — NO smem, NO barriers, NO cp.async. Each warp loads its MMA
// fragments directly from the fragment-blocked globals as coalesced 512B
// LDG.128s (L2-resident; 12-deep MLP per sp + 4 desynced warps/SMSP hide
// the ~240cyc L2 latency). LPT items from g_items.
// ---------------------------------------------------------------------------
__global__ __launch_bounds__(256, 2)
void quad_tc_kernel(const float* __restrict__ X, float* __restrict__ out) {
    const int tid  = threadIdx.x;
    const int lane = tid & 31;
    const int w    = tid >> 5;
    const int g    = lane >> 2;
    const int q    = lane & 3;
    const int wm   = w & 1;       // 0..1 : 64 batch rows
    const int wn   = w >> 1;      // 0..3 : 32 j cols

    const int4 item = g_items[blockIdx.x];
    const int jt  = item.x;
    const int bt  = item.y;
    const int kc0 = item.z;
    const int len = item.w;

    const int b0 = bt << 7;
    const int j0 = jt << 7;

    // byte offsets of the (rg, kc0, sp=0) blocks, + lane*16
    const uint32_t laneB = (uint32_t)lane * 16;
    uint32_t aOff[8];   // [mt*2 + h]
    #pragma unroll
    for (int mt = 0; mt < 4; mt++)
        #pragma unroll
        for (int h = 0; h < 2; h++) {
            const int rg = (b0 >> 3) + wm * 8 + mt * 2 + h;
            aOff[mt * 2 + h] = (uint32_t)((rg * KC64 + kc0) * 1024) + laneB;
        }
    uint32_t bOff[4];   // [nt]
    #pragma unroll
    for (int nt = 0; nt < 4; nt++) {
        const int rg = (j0 >> 3) + wn * 4 + nt;
        bOff[nt] = (uint32_t)((rg * KC64 + kc0) * 1024) + laneB;
    }
    const char* gA = (const char*)g_Xp;
    const char* gB = (const char*)g_Tp;

    float acc[4][4][4];
    #pragma unroll
    for (int mt = 0; mt < 4; mt++)
        #pragma unroll
        for (int nt = 0; nt < 4; nt++)
            #pragma unroll
            for (int c = 0; c < 4; c++) acc[mt][nt][c] = 0.f;

    for (int ks = 0; ks < len; ks++) {
        #pragma unroll
        for (int sp = 0; sp < 2; sp++) {
            uint4 bf[4];
            #pragma unroll
            for (int nt = 0; nt < 4; nt++)
                bf[nt] = *reinterpret_cast<const uint4*>(gB + bOff[nt] + sp * 512);
            uint4 af[8];
            #pragma unroll
            for (int s8 = 0; s8 < 8; s8++)
                af[s8] = *reinterpret_cast<const uint4*>(gA + aOff[s8] + sp * 512);
            #pragma unroll
            for (int t = 0; t < 2; t++) {
                #pragma unroll
                for (int mt = 0; mt < 4; mt++) {
                    const uint4 al = af[mt * 2 + 0];
                    const uint4 ah = af[mt * 2 + 1];
                    const uint32_t a0 = t ? al.z : al.x;
                    const uint32_t a2 = t ? al.w : al.y;
                    const uint32_t a1 = t ? ah.z : ah.x;
                    const uint32_t a3 = t ? ah.w : ah.y;
                    #pragma unroll
                    for (int nt = 0; nt < 4; nt++) {
                        const uint32_t b0r = t ? bf[nt].z : bf[nt].x;
                        const uint32_t b1r = t ? bf[nt].w : bf[nt].y;
                        mma_f16(acc[mt][nt], a0, a1, a2, a3, b0r, b1r);
                    }
                }
            }
        }
        #pragma unroll
        for (int s8 = 0; s8 < 8; s8++) aOff[s8] += 1024;
        #pragma unroll
        for (int nt = 0; nt < 4; nt++) bOff[nt] += 1024;
    }

    // fused epilogue: out[b] += (1/TSCALE) * sum_j Ypartial[b,j] * X[b,j]
    #pragma unroll
    for (int mt = 0; mt < 4; mt++) {
        #pragma unroll
        for (int hh = 0; hh < 2; hh++) {
            const int b = b0 + wm * 64 + mt * 16 + g + 8 * hh;
            const float* xr = X + (size_t)b * LC + j0 + wn * 32;
            float s = 0.f;
            #pragma unroll
            for (int nt = 0; nt < 4; nt++) {
                float2 xv = *reinterpret_cast<const float2*>(xr + nt * 8 + 2 * q);
                s += acc[mt][nt][2 * hh] * xv.x + acc[mt][nt][2 * hh + 1] * xv.y;
            }
            s += __shfl_xor_sync(0xffffffffu, s, 1);
            s += __shfl_xor_sync(0xffffffffu, s, 2);
            if (q == 0) atomicAdd(&out[b], s * (1.0f / TSCALE));
        }
    }
}

// ---------------------------------------------------------------------------
// Inputs: x_lc (B,L,C) f32 | theta_0 (1,) | theta_lc (1,L,C) |
//         theta_lclc (1,L,C,L,C) pre-masked f32 | mask (unused)
// Output: (B,1) f32
// ---------------------------------------------------------------------------
extern "C" void kernel_launch(void* const* d_in, const int* in_sizes, int n_in,
                              void* d_out, int out_size) {
    const float* x      = (const float*)d_in[0];
    const float* th0    = (const float*)d_in[1];
    const float* thlc   = (const float*)d_in[2];
    const float* thlclc = (const float*)d_in[3];
    float* out = (float*)d_out;

    prep_all<<<NT_TILES + B_DIM, 256>>>(x, th0, thlc, thlclc, out);
    quad_tc_kernel<<<NITEMS, 256>>>(x, out);
}

// round 17
// speedup vs baseline: 1.3920x; 1.3920x over previous
#include <cuda_runtime.h>
#include <cuda_fp16.h>
#include <cstdint>

#define B_DIM 1024
#define C_DIM 20
#define LC    5120
#define KC64  80           // LC / 64 K-chunks
#define TSCALE 256.0f
#define NT_TILES 3200      // prep_T tiles: 80(i) x 40(j)
#define NITEMS 480         // quad work items

// ---------------------------------------------------------------------------
// Scratch: fp16 pairs, K-major, pair-permuted within each 64-chunk.
// word(pl): c=pl>>3, pc=pl&7 -> w = (pc&3)*8 + c*2 + (pc>>2)
// g_Tp zero-initialized; masked tiles never written -> stay zero.
// g_items: LPT-ordered work schedule {jt, bt, kc0, len}, written by prep_all.
// ---------------------------------------------------------------------------
__device__ uint32_t g_Xp[(size_t)B_DIM * LC / 2];
__device__ uint32_t g_Tp[(size_t)LC * LC / 2];
__device__ int4     g_items[NITEMS];

__device__ __forceinline__ uint32_t smem_u32(const void* p) {
    uint32_t a;
    asm("{ .reg .u64 t; cvta.to.shared.u64 t, %1; cvt.u32.u64 %0, t; }"
        : "=r"(a) : "l"(p));
    return a;
}
__device__ __forceinline__ void cpa16(uint32_t dst, const void* gsrc) {
    asm volatile("cp.async.cg.shared.global [%0], [%1], 16;"
                 :: "r"(dst), "l"(__cvta_generic_to_global(gsrc)));
}
__device__ __forceinline__ void cpa16o(uint32_t dst, const char* gbase, uint32_t goff) {
    asm volatile("cp.async.cg.shared.global [%0], [%1], 16;"
                 :: "r"(dst), "l"(__cvta_generic_to_global(gbase + goff)));
}
#define CP_COMMIT() asm volatile("cp.async.commit_group;" ::: "memory")
#define CP_WAIT1()  asm volatile("cp.async.wait_group 1;" ::: "memory")
#define CP_WAIT0()  asm volatile("cp.async.wait_group 0;" ::: "memory")

__device__ __forceinline__ void mma_f16(float c[4],
                                        uint32_t a0, uint32_t a1,
                                        uint32_t a2, uint32_t a3,
                                        uint32_t b0, uint32_t b1) {
    asm("mma.sync.aligned.m16n8k16.row.col.f32.f16.f16.f32 "
        "{%0,%1,%2,%3}, {%4,%5,%6,%7}, {%8,%9}, {%0,%1,%2,%3};"
        : "+f"(c[0]), "+f"(c[1]), "+f"(c[2]), "+f"(c[3])
        : "r"(a0), "r"(a1), "r"(a2), "r"(a3), "r"(b0), "r"(b1));
}

__device__ __forceinline__ int pair_word(int pl) {
    const int c  = pl >> 3;
    const int pc = pl & 7;
    return (pc & 3) * 8 + c * 2 + (pc >> 2);
}

__device__ __forceinline__ int kpp_of(int jt) {
    const int Kmax = ((jt * 128 + 127) / C_DIM) * C_DIM;
    return (Kmax + 63) >> 6;
}

// ---------------------------------------------------------------------------
// Merged prep kernel: prep_T tiles (cp.async-staged), prep_X + init out,
// and the LPT quad schedule (first prep_X block).
// ---------------------------------------------------------------------------
__global__ __launch_bounds__(256)
void prep_all(const float* __restrict__ X,
              const float* __restrict__ th0,
              const float* __restrict__ thlc,
              const float* __restrict__ T,
              float* __restrict__ out) {
    const int blk = blockIdx.x;
    const int t   = threadIdx.x;

    if (blk < NT_TILES) {
        const int it = blk % (LC / 64);
        const int jt = blk / (LC / 64);
        const int i0 = it * 64;
        const int j0 = jt * 128;
        const int bound = ((j0 + 127) / C_DIM) * C_DIM;
        if (i0 >= bound) return;

        __shared__ float tile[64][132];
        const uint32_t tb = smem_u32(&tile[0][0]);
        // stage the 64x128 f32 tile via cp.async (8 x 16B per thread)
        {
            const int row = t >> 2;             // 0..63
            const int c16 = t & 3;              // 16B-chunk phase
            const float* src = T + (size_t)(i0 + row) * LC + j0;
            const uint32_t drow = tb + (uint32_t)row * (132 * 4);
            #pragma unroll
            for (int rr = 0; rr < 8; rr++) {
                const int col4 = c16 + rr * 4;  // 0..31 (x4 floats)
                cpa16(drow + col4 * 16, src + col4 * 4);
            }
        }
        CP_COMMIT();
        CP_WAIT0();
        __syncthreads();

        const int jl   = t >> 1;                // 0..127
        const int half = t & 1;
        const int wb   = half * 16;
        uint32_t buf[16];
        #pragma unroll
        for (int dw = 0; dw < 16; dw++) {
            const int w  = wb + dw;
            const int c  = (w & 7) >> 1;
            const int pc = ((w & 1) << 2) | (w >> 3);
            const int pl = (c << 3) | pc;
            const float v0 = tile[2 * pl][jl] * TSCALE;
            const float v1 = tile[2 * pl + 1][jl] * TSCALE;
            __half2 h = __floats2half2_rn(v0, v1);
            buf[dw] = *reinterpret_cast<uint32_t*>(&h);
        }
        uint32_t* dst = g_Tp + ((size_t)(j0 + jl) * KC64 + it) * 32 + wb;
        #pragma unroll
        for (int v = 0; v < 4; v++)
            *reinterpret_cast<uint4*>(dst + v * 4) =
                *reinterpret_cast<const uint4*>(&buf[v * 4]);
    } else {
        const int b = blk - NT_TILES;

        if (b == 0) {
            for (int idx = t; idx < NITEMS; idx += 256) {
                int is = 0, ifu = 0, base = 0;
                int jt = 0, bt = 0, kc0 = 0, len = 0;
                for (int step = 0; step < 60; step++) {
                    int lenS = -1, kppS = 0, jtS = 0;
                    if (is < 40) {
                        jtS  = 39 - (is >> 1);
                        kppS = kpp_of(jtS);
                        lenS = (is & 1) ? (kppS >> 1) : (kppS - (kppS >> 1));
                    }
                    int lenF = -1, jtF = 0;
                    if (ifu < 20) { jtF = 19 - ifu; lenF = kpp_of(jtF); }
                    const bool takeS = (is < 40) && (ifu >= 20 || lenS >= lenF);
                    if (idx < base + 8) {
                        bt = idx - base;
                        if (takeS) {
                            jt  = jtS;
                            len = lenS;
                            kc0 = (is & 1) ? (kppS - (kppS >> 1)) : 0;
                        } else {
                            jt = jtF; len = lenF; kc0 = 0;
                        }
                        break;
                    }
                    base += 8;
                    if (takeS) is++; else ifu++;
                }
                g_items[idx] = make_int4(jt, bt, kc0, len);
            }
        }

        const float* xr = X + (size_t)b * LC;
        float s = 0.f;
        for (int k4 = t; k4 < LC / 4; k4 += 256) {
            const float4 xv = *reinterpret_cast<const float4*>(xr + k4 * 4);
            const float4 tv = *reinterpret_cast<const float4*>(thlc + k4 * 4);
            s += xv.x * tv.x + xv.y * tv.y + xv.z * tv.z + xv.w * tv.w;
            const int k  = k4 * 4;
            const int kc = k >> 6;
            const int pl = (k & 63) >> 1;
            uint32_t* base = g_Xp + ((size_t)b * KC64 + kc) * 32;
            __half2 h0 = __floats2half2_rn(xv.x, xv.y);
            __half2 h1 = __floats2half2_rn(xv.z, xv.w);
            base[pair_word(pl)]     = *reinterpret_cast<uint32_t*>(&h0);
            base[pair_word(pl + 1)] = *reinterpret_cast<uint32_t*>(&h1);
        }
        for (int o = 16; o > 0; o >>= 1) s += __shfl_xor_sync(0xffffffffu, s, o);
        __shared__ float red[8];
        if ((t & 31) == 0) red[t >> 5] = s;
        __syncthreads();
        if (t == 0) {
            float tt = 0.f;
            #pragma unroll
            for (int w = 0; w < 8; w++) tt += red[w];
            out[b] = th0[0] + tt;
        }
    }
}

// ---------------------------------------------------------------------------
// quad kernel — R13 body, byte-for-byte (banked best: one barrier/chunk,
// end-of-body prefetch, LPT items from g_items).
// ---------------------------------------------------------------------------
#define STAGE_BYTES 36864
#define BOFF        18432
#define SMEM_TOTAL  (3 * STAGE_BYTES)

__global__ __launch_bounds__(256, 2)
void quad_tc_kernel(const float* __restrict__ X, float* __restrict__ out) {
    extern __shared__ char smem[];
    const uint32_t sb = smem_u32(smem);
    const int tid  = threadIdx.x;
    const int lane = tid & 31;
    const int w    = tid >> 5;
    const int g    = lane >> 2;
    const int q    = lane & 3;
    const int wm   = w & 1;
    const int wn   = w >> 1;

    const int4 item = g_items[blockIdx.x];
    const int jt  = item.x;
    const int bt  = item.y;
    const int kc0 = item.z;
    const int len = item.w;

    const int b0 = bt << 7;
    const int j0 = jt << 7;

    const int rowL = tid >> 3;
    const int ch   = tid & 7;
    uint32_t gAc[4], gBc[4];
    #pragma unroll
    for (int i = 0; i < 4; i++) {
        const int row = rowL + i * 32;
        gAc[i] = (uint32_t)((b0 + row) * (KC64 * 128) + kc0 * 128 + ch * 16);
        gBc[i] = (uint32_t)((j0 + row) * (KC64 * 128) + kc0 * 128 + ch * 16);
    }
    const uint32_t sAc = (uint32_t)(rowL * 144 + ch * 16);
    const char* gA = (const char*)g_Xp;
    const char* gB = (const char*)g_Tp;

    float acc[4][4][4];
    #pragma unroll
    for (int mt = 0; mt < 4; mt++)
        #pragma unroll
        for (int nt = 0; nt < 4; nt++)
            #pragma unroll
            for (int c = 0; c < 4; c++) acc[mt][nt][c] = 0.f;

    // prologue: chunks kc0, kc0+1 (len >= 2 always)
    #pragma unroll
    for (int s = 0; s < 2; s++) {
        const uint32_t st = sb + s * STAGE_BYTES + sAc;
        const uint32_t ko = (uint32_t)s * 128;
        #pragma unroll
        for (int i = 0; i < 4; i++) cpa16o(st + i * (32 * 144), gA, gAc[i] + ko);
        #pragma unroll
        for (int i = 0; i < 4; i++) cpa16o(st + BOFF + i * (32 * 144), gB, gBc[i] + ko);
        CP_COMMIT();
    }

    const uint32_t fA = (uint32_t)((wm * 64 + g) * 144 + q * 32);
    const uint32_t fB = (uint32_t)(BOFF + (wn * 32 + g) * 144 + q * 32);

    int ss = 0;
    for (int ks = 0; ks < len; ks++) {
        CP_WAIT1();
        __syncthreads();

        const char* aB = smem + ss * STAGE_BYTES;
        #pragma unroll
        for (int sp = 0; sp < 2; sp++) {
            uint4 bf[4];
            #pragma unroll
            for (int nt = 0; nt < 4; nt++)
                bf[nt] = *reinterpret_cast<const uint4*>(aB + fB + nt * (8 * 144) + sp * 16);
            #pragma unroll
            for (int mt = 0; mt < 4; mt++) {
                const char* ap = aB + fA + mt * (16 * 144) + sp * 16;
                uint4 al = *reinterpret_cast<const uint4*>(ap);
                uint4 ah = *reinterpret_cast<const uint4*>(ap + 8 * 144);
                #pragma unroll
                for (int t = 0; t < 2; t++) {
                    const uint32_t a0 = t ? al.z : al.x;
                    const uint32_t a2 = t ? al.w : al.y;
                    const uint32_t a1 = t ? ah.z : ah.x;
                    const uint32_t a3 = t ? ah.w : ah.y;
                    #pragma unroll
                    for (int nt = 0; nt < 4; nt++) {
                        const uint32_t b0r = t ? bf[nt].z : bf[nt].x;
                        const uint32_t b1r = t ? bf[nt].w : bf[nt].y;
                        mma_f16(acc[mt][nt], a0, a1, a2, a3, b0r, b1r);
                    }
                }
            }
        }
        if (ks + 2 < len) {
            const int s2 = (ss + 2 >= 3) ? ss - 1 : ss + 2;
            const uint32_t st = sb + s2 * STAGE_BYTES + sAc;
            const uint32_t ko = (uint32_t)(ks + 2) * 128;
            #pragma unroll
            for (int i = 0; i < 4; i++) cpa16o(st + i * (32 * 144), gA, gAc[i] + ko);
            #pragma unroll
            for (int i = 0; i < 4; i++) cpa16o(st + BOFF + i * (32 * 144), gB, gBc[i] + ko);
        }
        CP_COMMIT();
        ss = (ss + 1 >= 3) ? 0 : ss + 1;
    }

    // fused epilogue: out[b] += (1/TSCALE) * sum_j Ypartial[b,j] * X[b,j]
    #pragma unroll
    for (int mt = 0; mt < 4; mt++) {
        #pragma unroll
        for (int hh = 0; hh < 2; hh++) {
            const int b = b0 + wm * 64 + mt * 16 + g + 8 * hh;
            const float* xr = X + (size_t)b * LC + j0 + wn * 32;
            float s = 0.f;
            #pragma unroll
            for (int nt = 0; nt < 4; nt++) {
                const float2 xv = __ldg(reinterpret_cast<const float2*>(xr + nt * 8 + 2 * q));
                s += acc[mt][nt][2 * hh] * xv.x + acc[mt][nt][2 * hh + 1] * xv.y;
            }
            s += __shfl_xor_sync(0xffffffffu, s, 1);
            s += __shfl_xor_sync(0xffffffffu, s, 2);
            if (q == 0) atomicAdd(&out[b], s * (1.0f / TSCALE));
        }
    }
}

// ---------------------------------------------------------------------------
// Inputs: x_lc (B,L,C) f32 | theta_0 (1,) | theta_lc (1,L,C) |
//         theta_lclc (1,L,C,L,C) pre-masked f32 | mask (unused)
// Output: (B,1) f32
// ---------------------------------------------------------------------------
extern "C" void kernel_launch(void* const* d_in, const int* in_sizes, int n_in,
                              void* d_out, int out_size) {
    const float* x      = (const float*)d_in[0];
    const float* th0    = (const float*)d_in[1];
    const float* thlc   = (const float*)d_in[2];
    const float* thlclc = (const float*)d_in[3];
    float* out = (float*)d_out;

    cudaFuncSetAttribute(quad_tc_kernel,
                         cudaFuncAttributeMaxDynamicSharedMemorySize, SMEM_TOTAL);

    prep_all<<<NT_TILES + B_DIM, 256>>>(x, th0, thlc, thlclc, out);
    quad_tc_kernel<<<NITEMS, 256, SMEM_TOTAL>>>(x, out);
}